// round 2
// baseline (speedup 1.0000x reference)
#include <cuda_runtime.h>

// AttentionOptimizer: out = spins - LR*(grads + SMOOTH*g_smooth) + noise
// g_smooth = conv3(u)/conv3(v),  u = g*exp(-BETA*|g|), v = exp(-BETA*|g|),
// conv3 = separable kernel w[d] = exp(-(5/L^2)*(d*2/(L-1))^2) per axis.
// (beta*gn_i row term cancels in the softmax; distance term is separable.)
//
// R2: z-line stride padded 20 -> 21 float2 so pass-1 lane stride is 42 words
// (2-way bank conflict) instead of 40 words (8-way). Layout:
//   idx(x,y,z) = (x*20 + y)*21 + z   [float2 units]

#define LLAT 20
#define LPAD 21                  // padded z stride (float2 units)
#define NLINES 400               // LLAT*LLAT
#define NPTS 8000                // LLAT^3
#define NPADPTS (NLINES * LPAD)  // 8400

// Packed f32x2 FMA (sm_103a): d = a*b + c on both lanes.
static __device__ __forceinline__ float2 fma2(float2 a, float2 b, float2 c) {
    float2 d;
    asm("fma.rn.f32x2 %0, %1, %2, %3;"
        : "=l"(*reinterpret_cast<unsigned long long*>(&d))
        : "l"(*reinterpret_cast<unsigned long long*>(&a)),
          "l"(*reinterpret_cast<unsigned long long*>(&b)),
          "l"(*reinterpret_cast<unsigned long long*>(&c)));
    return d;
}

// One full conv line: 20 outputs from 20 taps, diagonal-ordered so each
// distinct weight w[i-j] is one broadcast LDS.64 per diagonal. The bounds
// check resolves at compile time after full unroll (no predication).
template <int SA>
static __device__ __forceinline__ void convLine(
    const float2* __restrict__ in, float2* __restrict__ outp,
    const float2* __restrict__ w2, int base)
{
    float2 tap[LLAT];
#pragma unroll
    for (int j = 0; j < LLAT; j++) tap[j] = in[base + j * SA];

    float2 acc[LLAT];
#pragma unroll
    for (int i = 0; i < LLAT; i++) acc[i] = make_float2(0.0f, 0.0f);

#pragma unroll
    for (int dd = 0; dd < 2 * LLAT - 1; dd++) {     // d = i - j = dd - 19
        const float2 w = w2[dd];
#pragma unroll
        for (int i = 0; i < LLAT; i++) {
            const int j = i - (dd - (LLAT - 1));
            if (j >= 0 && j < LLAT)
                acc[i] = fma2(tap[j], w, acc[i]);
        }
    }
#pragma unroll
    for (int i = 0; i < LLAT; i++) outp[base + i * SA] = acc[i];
}

__global__ void __launch_bounds__(512, 1)
attn_opt_kernel(const float* __restrict__ grads,
                const float* __restrict__ spins,
                const float* __restrict__ noise,
                float* __restrict__ out)
{
    extern __shared__ float2 smemBuf[];
    float2* A  = smemBuf;                 // NPADPTS float2
    float2* Bv = smemBuf + NPADPTS;       // NPADPTS float2
    float2* w2 = smemBuf + 2 * NPADPTS;   // 39 float2 (dup-packed weights)

    const int b = blockIdx.x;
    const float* gb = grads + b * NPTS;
    const int t = threadIdx.x;

    // Weight table: w[d] = exp(-0.0125 * (d * 2/19)^2), d in [-19, 19]
    if (t < 2 * LLAT - 1) {
        const float d = (float)(t - (LLAT - 1)) * (2.0f / (float)(LLAT - 1));
        const float w = __expf(-0.0125f * d * d);
        w2[t] = make_float2(w, w);
    }

    // Prologue: u = g * exp(-2|g|), v = exp(-2|g|)  (padded layout)
    for (int i = t; i < NPTS; i += 512) {
        const int line = i / LLAT;
        const int z    = i - line * LLAT;
        const float gv = gb[i];
        const float e  = __expf(-2.0f * fabsf(gv));
        A[line * LPAD + z] = make_float2(gv * e, e);
    }
    __syncthreads();

    // Pass 1: conv along z (stride 1). line t=(x*20+y), base = t*21.
    if (t < NLINES) convLine<1>(A, Bv, w2, t * LPAD);
    __syncthreads();

    // Pass 2: conv along y (stride 21). t -> (x = t/20, z = t%20).
    if (t < NLINES) {
        const int x = t / LLAT;
        const int z = t - x * LLAT;
        convLine<LPAD>(Bv, A, w2, x * (LLAT * LPAD) + z);
    }
    __syncthreads();

    // Pass 3: conv along x (stride 420). t -> (y = t/20, z = t%20).
    if (t < NLINES) {
        const int y = t / LLAT;
        const int z = t - y * LLAT;
        convLine<LLAT * LPAD>(A, Bv, w2, y * LPAD + z);
    }
    __syncthreads();

    // Epilogue: out = spins - 0.05*(g + 10 * u/v) + noise
    const float* sb = spins + b * NPTS;
    const float* nb = noise + b * NPTS;
    float* ob = out + b * NPTS;
    for (int i = t; i < NPTS; i += 512) {
        const int line = i / LLAT;
        const int z    = i - line * LLAT;
        const float2 r = Bv[line * LPAD + z];
        const float gs = __fdividef(r.x, r.y);
        ob[i] = sb[i] - 0.05f * (gb[i] + 10.0f * gs) + nb[i];
    }
}

extern "C" void kernel_launch(void* const* d_in, const int* in_sizes, int n_in,
                              void* d_out, int out_size)
{
    const float* grads = (const float*)d_in[0];
    const float* spins = (const float*)d_in[1];
    // d_in[2] = pos: unused — lattice geometry is known analytically.
    const float* noise = (const float*)d_in[3];
    float* out = (float*)d_out;

    const int B = in_sizes[0] / NPTS;
    const size_t smem = (size_t)(2 * NPADPTS + 2 * LLAT - 1) * sizeof(float2); // ~134.7 KB

    cudaFuncSetAttribute(attn_opt_kernel,
                         cudaFuncAttributeMaxDynamicSharedMemorySize, (int)smem);
    attn_opt_kernel<<<B, 512, smem>>>(grads, spins, noise, out);
}

// round 3
// speedup vs baseline: 1.9211x; 1.9211x over previous
#include <cuda_runtime.h>

// AttentionOptimizer: out = spins - LR*(grads + SMOOTH*g_smooth) + noise
// g_smooth = conv3(u)/conv3(v),  u = g*exp(-BETA*|g|), v = exp(-BETA*|g|),
// separable per-axis kernel w[d] = exp(-0.0125*(d*2/19)^2).
//
// R3: split across 2 kernels / 40 CTAs each.
//  Kernel A: CTA per (b, x): z-conv then y-conv on the [y][z] plane (smem),
//            writes scratch transposed to [b][y][x][z].
//  Kernel B: CTA per (b, y): x-conv on the [x][z] plane + fused epilogue.

#define LLAT 20
#define PLANE 400                 // LLAT*LLAT
#define NPTS 8000                 // LLAT^3
#define MAXB 8

__device__ float2 g_scratch[MAXB * NPTS];   // [b][y][x][z] (float2 = {u,v})

// Packed f32x2 FMA (sm_103a): d = a*b + c on both lanes.
static __device__ __forceinline__ float2 fma2(float2 a, float2 b, float2 c) {
    float2 d;
    asm("fma.rn.f32x2 %0, %1, %2, %3;"
        : "=l"(*reinterpret_cast<unsigned long long*>(&d))
        : "l"(*reinterpret_cast<unsigned long long*>(&a)),
          "l"(*reinterpret_cast<unsigned long long*>(&b)),
          "l"(*reinterpret_cast<unsigned long long*>(&c)));
    return d;
}

static __device__ __forceinline__ void fillWeights(float2* w2, int t) {
    if (t < 2 * LLAT - 1) {
        const float d = (float)(t - (LLAT - 1)) * (2.0f / (float)(LLAT - 1));
        const float w = __expf(-0.0125f * d * d);
        w2[t] = make_float2(w, w);
    }
}

// ── Kernel A: prologue + z-conv + y-conv on one x-plane ────────────────────
__global__ void __launch_bounds__(PLANE, 4)
passA_kernel(const float* __restrict__ grads)
{
    __shared__ float2 U[PLANE];
    __shared__ float2 T[PLANE];
    __shared__ float2 w2[2 * LLAT - 1];

    const int t  = threadIdx.x;          // t = y*20 + z
    const int b  = blockIdx.x / LLAT;
    const int x  = blockIdx.x - b * LLAT;
    const int y  = t / LLAT;
    const int z  = t - y * LLAT;

    fillWeights(w2, t);

    // u = g*exp(-2|g|), v = exp(-2|g|)
    const float gv = grads[b * NPTS + x * PLANE + t];
    const float e  = __expf(-2.0f * fabsf(gv));
    U[t] = make_float2(gv * e, e);
    __syncthreads();

    // z-conv: T[y][z] = sum_j w[z-j] * U[y][j]
    float2 acc = make_float2(0.0f, 0.0f);
#pragma unroll
    for (int j = 0; j < LLAT; j++)
        acc = fma2(U[y * LLAT + j], w2[(LLAT - 1) + z - j], acc);
    T[t] = acc;
    __syncthreads();

    // y-conv: R[y][z] = sum_j w[y-j] * T[j][z]
    acc = make_float2(0.0f, 0.0f);
#pragma unroll
    for (int j = 0; j < LLAT; j++)
        acc = fma2(T[j * LLAT + z], w2[(LLAT - 1) + y - j], acc);

    // scratch[b][y][x][z] (transposed so kernel B reads contiguous planes)
    g_scratch[((b * LLAT + y) * LLAT + x) * LLAT + z] = acc;
}

// ── Kernel B: x-conv on one y-plane + fused epilogue ───────────────────────
__global__ void __launch_bounds__(PLANE, 4)
passB_kernel(const float* __restrict__ grads,
             const float* __restrict__ spins,
             const float* __restrict__ noise,
             float* __restrict__ out)
{
    __shared__ float2 U[PLANE];
    __shared__ float2 w2[2 * LLAT - 1];

    const int t  = threadIdx.x;          // t = x*20 + z
    const int b  = blockIdx.x / LLAT;
    const int y  = blockIdx.x - b * LLAT;
    const int x  = t / LLAT;
    const int z  = t - x * LLAT;

    fillWeights(w2, t);

    // contiguous plane load: scratch[b][y][x][z]
    U[t] = g_scratch[(b * LLAT + y) * PLANE + t];
    __syncthreads();

    // x-conv: R[x][z] = sum_j w[x-j] * U[j][z]
    float2 acc = make_float2(0.0f, 0.0f);
#pragma unroll
    for (int j = 0; j < LLAT; j++)
        acc = fma2(U[j * LLAT + z], w2[(LLAT - 1) + x - j], acc);

    // epilogue at global index [b][x][y][z]
    const int gi = ((b * LLAT + x) * LLAT + y) * LLAT + z;
    const float gs = __fdividef(acc.x, acc.y);
    out[gi] = spins[gi] - 0.05f * (grads[gi] + 10.0f * gs) + noise[gi];
}

extern "C" void kernel_launch(void* const* d_in, const int* in_sizes, int n_in,
                              void* d_out, int out_size)
{
    const float* grads = (const float*)d_in[0];
    const float* spins = (const float*)d_in[1];
    // d_in[2] = pos: unused — lattice geometry is known analytically.
    const float* noise = (const float*)d_in[3];
    float* out = (float*)d_out;

    const int B = in_sizes[0] / NPTS;

    passA_kernel<<<B * LLAT, PLANE>>>(grads);
    passB_kernel<<<B * LLAT, PLANE>>>(grads, spins, noise, out);
}

// round 4
// speedup vs baseline: 2.1789x; 1.1341x over previous
#include <cuda_runtime.h>

// AttentionOptimizer: out = spins - LR*(grads + SMOOTH*g_smooth) + noise
// g_smooth = conv3(u)/conv3(v),  u = g*exp(-BETA*|g|), v = exp(-BETA*|g|),
// separable per-axis kernel w[d] = exp(-0.0125*(d*2/19)^2).
//
// R4: SINGLE kernel, one CTA per (b, y_out). The y-axis reduction is done
// FIRST (weights depend only on y_out, fixed per CTA), redundantly per CTA,
// directly from grads -> no inter-pass kernel boundary, no scratch, one
// launch overhead. Then z-conv and x-conv run in the CTA's own smem plane.

#define LLAT 20
#define PLANE 400                 // LLAT*LLAT
#define NPTS 8000                 // LLAT^3

// Packed f32x2 FMA (sm_103a): d = a*b + c on both lanes.
static __device__ __forceinline__ float2 fma2(float2 a, float2 b, float2 c) {
    float2 d;
    asm("fma.rn.f32x2 %0, %1, %2, %3;"
        : "=l"(*reinterpret_cast<unsigned long long*>(&d))
        : "l"(*reinterpret_cast<unsigned long long*>(&a)),
          "l"(*reinterpret_cast<unsigned long long*>(&b)),
          "l"(*reinterpret_cast<unsigned long long*>(&c)));
    return d;
}

__global__ void __launch_bounds__(PLANE, 1)
attn_opt_fused(const float* __restrict__ grads,
               const float* __restrict__ spins,
               const float* __restrict__ noise,
               float* __restrict__ out)
{
    __shared__ float2 V[PLANE];
    __shared__ float2 T[PLANE];
    __shared__ float2 w2[2 * LLAT - 1];

    const int t  = threadIdx.x;              // t = xp*20 + zp
    const int b  = blockIdx.x / LLAT;
    const int yo = blockIdx.x - b * LLAT;    // output y-plane
    const int xp = t / LLAT;
    const int zp = t - xp * LLAT;

    // Hoisted epilogue operands: DRAM latency hides under the conv chain.
    const int gi = b * NPTS + xp * PLANE + yo * LLAT + zp;
    const float s_v = spins[gi];
    const float n_v = noise[gi];
    const float g_v = grads[gi];

    // Weight table: w[d] = exp(-0.0125*(d*2/19)^2), d in [-19,19], dup-packed.
    if (t < 2 * LLAT - 1) {
        const float d = (float)(t - (LLAT - 1)) * (2.0f / (float)(LLAT - 1));
        const float w = __expf(-0.0125f * d * d);
        w2[t] = make_float2(w, w);
    }

    // Phase 1: y-reduction with y_out-dependent weights, straight from grads.
    // Load the 20-deep g column first (MLP=20), then transform + reduce.
    const float* gcol = grads + b * NPTS + xp * PLANE + zp;
    float gc[LLAT];
#pragma unroll
    for (int yp = 0; yp < LLAT; yp++) gc[yp] = gcol[yp * LLAT];

    __syncthreads();   // w2 ready

    float2 acc = make_float2(0.0f, 0.0f);
#pragma unroll
    for (int yp = 0; yp < LLAT; yp++) {
        const float e = __expf(-2.0f * fabsf(gc[yp]));
        const float2 ue = make_float2(gc[yp] * e, e);
        acc = fma2(ue, w2[(LLAT - 1) + yo - yp], acc);   // broadcast LDS.64
    }
    V[t] = acc;
    __syncthreads();

    // Phase 2: z-conv within the plane. T[xp][zp] = sum_j w[zp-j] V[xp][j]
    acc = make_float2(0.0f, 0.0f);
#pragma unroll
    for (int j = 0; j < LLAT; j++)
        acc = fma2(V[xp * LLAT + j], w2[(LLAT - 1) + zp - j], acc);
    T[t] = acc;
    __syncthreads();

    // Phase 3: x-conv. R[xp][zp] = sum_j w[xp-j] T[j][zp]
    acc = make_float2(0.0f, 0.0f);
#pragma unroll
    for (int j = 0; j < LLAT; j++)
        acc = fma2(T[j * LLAT + zp], w2[(LLAT - 1) + xp - j], acc);

    // Epilogue: out = s - 0.05*g - 0.5*(u/v) + n
    out[gi] = s_v - 0.05f * g_v - 0.5f * __fdividef(acc.x, acc.y) + n_v;
}

extern "C" void kernel_launch(void* const* d_in, const int* in_sizes, int n_in,
                              void* d_out, int out_size)
{
    const float* grads = (const float*)d_in[0];
    const float* spins = (const float*)d_in[1];
    // d_in[2] = pos: unused — lattice geometry is known analytically.
    const float* noise = (const float*)d_in[3];
    float* out = (float*)d_out;

    const int B = in_sizes[0] / NPTS;
    attn_opt_fused<<<B * LLAT, PLANE>>>(grads, spins, noise, out);
}